// round 4
// baseline (speedup 1.0000x reference)
#include <cuda_runtime.h>
#include <cstdint>

// out[e, 0:128]   = node_states[src[e], :]
// out[e, 128:256] = node_states[tgt[e], :]
// One warp per FOUR edges: int4 index loads (1 per array per warp),
// 8 independent row-gathers in flight (MLP=8), 8 STG.128 streaming stores.
// Steady-state binder: 328 MB DRAM write stream (83% of spec at 49.6us).

__global__ __launch_bounds__(256) void node_propagate_kernel(
    const float4* __restrict__ ns,   // [N_NODES, 32] as float4
    const int* __restrict__ src,     // [E] int32
    const int* __restrict__ tgt,     // [E] int32
    float4* __restrict__ out,        // [E, 64] as float4
    int E)
{
    const int gwarp = (int)((blockIdx.x * (unsigned)blockDim.x + threadIdx.x) >> 5);
    const int lane  = threadIdx.x & 31;
    const int e0    = gwarp * 4;
    if (e0 >= E) return;

    if (e0 + 3 < E) {
        // Fast path (all of E=320000 since 4 | E): full quad.
        const int4 s4 = *(const int4*)(src + e0);   // broadcast 16B load
        const int4 t4 = *(const int4*)(tgt + e0);

        // 8 independent gathers in flight; node_states (5.12 MB) is L2-resident.
        const float4 a0 = __ldg(&ns[(size_t)s4.x * 32 + lane]);
        const float4 b0 = __ldg(&ns[(size_t)t4.x * 32 + lane]);
        const float4 a1 = __ldg(&ns[(size_t)s4.y * 32 + lane]);
        const float4 b1 = __ldg(&ns[(size_t)t4.y * 32 + lane]);
        const float4 a2 = __ldg(&ns[(size_t)s4.z * 32 + lane]);
        const float4 b2 = __ldg(&ns[(size_t)t4.z * 32 + lane]);
        const float4 a3 = __ldg(&ns[(size_t)s4.w * 32 + lane]);
        const float4 b3 = __ldg(&ns[(size_t)t4.w * 32 + lane]);

        // Streaming stores: evict-first keeps node_states resident in L2.
        float4* o = out + (size_t)e0 * 64;
        __stcs(o +       lane, a0);
        __stcs(o +  32 + lane, b0);
        __stcs(o +  64 + lane, a1);
        __stcs(o +  96 + lane, b1);
        __stcs(o + 128 + lane, a2);
        __stcs(o + 160 + lane, b2);
        __stcs(o + 192 + lane, a3);
        __stcs(o + 224 + lane, b3);
    } else {
        // Tail (unused for E=320000, kept for generality).
        for (int e = e0; e < E; e++) {
            const int s = __ldg(&src[e]);
            const int t = __ldg(&tgt[e]);
            const float4 a = __ldg(&ns[(size_t)s * 32 + lane]);
            const float4 b = __ldg(&ns[(size_t)t * 32 + lane]);
            float4* o = out + (size_t)e * 64;
            __stcs(o + lane,      a);
            __stcs(o + 32 + lane, b);
        }
    }
}

extern "C" void kernel_launch(void* const* d_in, const int* in_sizes, int n_in,
                              void* d_out, int out_size)
{
    const float4* ns  = (const float4*)d_in[0];
    const int*    src = (const int*)d_in[1];
    const int*    tgt = (const int*)d_in[2];
    float4*       out = (float4*)d_out;

    const int E = in_sizes[1];  // 320000 edges

    const int threads = 256;                 // 8 warps -> 32 edges per block
    const int warps   = (E + 3) / 4;
    const int blocks  = (warps * 32 + threads - 1) / threads;

    node_propagate_kernel<<<blocks, threads>>>(ns, src, tgt, out, E);
}